// round 7
// baseline (speedup 1.0000x reference)
#include <cuda_runtime.h>
#include <math.h>

#define BB  16
#define NQ  256
#define NKV 256
#define DD  64
#define TILES 16
#define TK 16

__device__ float g_proj[BB * NKV * 3 * DD];

// ---------------------------------------------------------------------------
// Kernel A: proj = v_equi @ W_coord^T  (12288 rows of 64). grid=768, one
// 4-row quad per warp; v loads issued before Wt staging to overlap.
// ---------------------------------------------------------------------------
__global__ void __launch_bounds__(128) proj_kernel(const float* __restrict__ v,
                                                   const float* __restrict__ Wc) {
    __shared__ __align__(16) float Wt[64 * 66];
    __shared__ __align__(16) float vbuf[4][4][64];

    int t = threadIdx.x;
    int w = t >> 5, l = t & 31;
    int qd = blockIdx.x * 4 + w;

    float2 v0 = ((const float2*)(v + (size_t)(qd * 4 + 0) * 64))[l];
    float2 v1 = ((const float2*)(v + (size_t)(qd * 4 + 1) * 64))[l];
    float2 v2 = ((const float2*)(v + (size_t)(qd * 4 + 2) * 64))[l];
    float2 v3 = ((const float2*)(v + (size_t)(qd * 4 + 3) * 64))[l];

    for (int i = t; i < 4096; i += 128) {
        Wt[(i & 63) * 66 + (i >> 6)] = Wc[i];
    }

    vbuf[w][0][2 * l] = v0.x;  vbuf[w][0][2 * l + 1] = v0.y;
    vbuf[w][1][2 * l] = v1.x;  vbuf[w][1][2 * l + 1] = v1.y;
    vbuf[w][2][2 * l] = v2.x;  vbuf[w][2][2 * l + 1] = v2.y;
    vbuf[w][3][2 * l] = v3.x;  vbuf[w][3][2 * l + 1] = v3.y;
    __syncthreads();

    float ax[4] = {0.f, 0.f, 0.f, 0.f};
    float ay[4] = {0.f, 0.f, 0.f, 0.f};
    #pragma unroll
    for (int e4 = 0; e4 < 16; e4++) {
        float4 va[4];
        #pragma unroll
        for (int r = 0; r < 4; r++) va[r] = *(const float4*)&vbuf[w][r][e4 * 4];
        #pragma unroll
        for (int i = 0; i < 4; i++) {
            float2 wt = *(const float2*)(Wt + (e4 * 4 + i) * 66 + 2 * l);
            #pragma unroll
            for (int r = 0; r < 4; r++) {
                float fr = ((const float*)&va[r])[i];
                ax[r] = fmaf(fr, wt.x, ax[r]);
                ay[r] = fmaf(fr, wt.y, ay[r]);
            }
        }
    }
    #pragma unroll
    for (int r = 0; r < 4; r++) {
        ((float2*)(g_proj + (size_t)(qd * 4 + r) * 64))[l] = make_float2(ax[r], ay[r]);
    }
}

// ---------------------------------------------------------------------------
// Main kernel. CTA = (b, 8 q's), 8 warps. k-space split into 16 tiles of 16;
// each tile's proj (12KB) staged to smem ONCE and shared by all 8 q-warps
// (proj L2 traffic /8). klist sorted -> per-tile work is a contiguous klist
// range (boundaries jb[] from popc prefix). msg streamed via per-pair
// cp.async groups (distance 3 pairs). proj tiles double-buffered via
// LDG-early / STS-late. Wt + ao overlap projT smem after the main loop.
// ---------------------------------------------------------------------------
__global__ void __launch_bounds__(256, 4) attn_kernel(const float* __restrict__ msg,
                                                      const int*   __restrict__ adjm,
                                                      const float* __restrict__ Wa,
                                                      float*       __restrict__ out) {
    __shared__ __align__(16) float projT[2][TK][3][64];       // 24KB (epilogue: Wt+ao)
    __shared__ __align__(16) float4 ring[8][4][2][16];        // 16KB msg ring
    __shared__ unsigned char  klist[8][NKV];                  // 2KB
    __shared__ unsigned short jb[8][TILES + 1];               // per-warp tile bounds

    float* WtS = &projT[0][0][0][0];          // 64*65 floats = 4160
    float* aoS = WtS + 4160;                  // 24*64 floats = 1536 (total 5696 <= 6144)

    int t = threadIdx.x;
    int w = t >> 5, l = t & 31;
    int li = l & 15, h = l >> 4;
    int b = blockIdx.x >> 5;
    int qbase = (blockIdx.x & 31) << 3;
    int q = qbase + w;

    // ---- build mask, compact klist (uchar), tile boundaries jb ----
    const int* arow = adjm + (b * NQ + q) * NKV;
    unsigned mask[8];
    unsigned any = 0u;
    #pragma unroll
    for (int c = 0; c < 8; c++) {
        mask[c] = __ballot_sync(0xffffffffu, arow[c * 32 + l] != 0);
        any |= mask[c];
    }
    if (!any) {
        #pragma unroll
        for (int c = 0; c < 8; c++) mask[c] = 0xffffffffu;
    }
    {
        int pos = 0;
        #pragma unroll
        for (int c = 0; c < 8; c++) {
            unsigned m = mask[c];
            if ((m >> l) & 1u) {
                klist[w][pos + __popc(m & ((1u << l) - 1u))] = (unsigned char)(c * 32 + l);
            }
            pos += __popc(m);
        }
    }
    if (l <= TILES) {        // lane l computes jb[l] = #active k < 16*l
        int s = 0;
        #pragma unroll
        for (int c = 0; c < 8; c++) {
            if (c < (l >> 1)) s += __popc(mask[c]);
        }
        if (l & 1) s += __popc(mask[l >> 1] & 0xFFFFu);
        jb[w][l] = (unsigned short)s;
    }
    __syncwarp();

    const float4* msg4  = (const float4*)msg + (size_t)(b * NQ + q) * (NKV * 16);
    const float4* projG = (const float4*)g_proj + (size_t)b * (NKV * 48);
    float4* projS = (float4*)&projT[0][0][0][0];

    // ---- prefetch state (msg, per-pair cp.async groups) ----
    int tp = 0;
    while (tp < TILES && jb[w][tp] == jb[w][tp + 1]) tp++;
    int jsp = 0, jep = 0, pp = 0;
    if (tp < TILES) { jsp = jb[w][tp]; jep = jb[w][tp + 1]; }

#define PSTEP(slot_)                                                           \
    do {                                                                       \
        if (tp < TILES) {                                                      \
            int pidx = jsp + 2 * pp + h;                                       \
            int pk = klist[w][(pidx < jep) ? pidx : (jep - 1)];                \
            unsigned dsta = (unsigned)__cvta_generic_to_shared(&ring[w][slot_][h][li]); \
            const float4* srcp = msg4 + pk * 16 + li;                          \
            asm volatile("cp.async.cg.shared.global [%0], [%1], 16;"           \
                         :: "r"(dsta), "l"(srcp) : "memory");                  \
            pp++;                                                              \
            if (jsp + 2 * pp >= jep) {                                         \
                pp = 0;                                                        \
                do { tp++; } while (tp < TILES && jb[w][tp] == jb[w][tp + 1]); \
                if (tp < TILES) { jsp = jb[w][tp]; jep = jb[w][tp + 1]; }      \
            }                                                                  \
        }                                                                      \
        asm volatile("cp.async.commit_group;" ::: "memory");                   \
    } while (0)

    PSTEP(0); PSTEP(1); PSTEP(2);      // distance = 3 pairs

    // ---- stage proj tile 0 ----
    projS[t]       = projG[t];
    projS[t + 256] = projG[t + 256];
    projS[t + 512] = projG[t + 512];
    __syncthreads();

    float dn[4] = {0.f, 0.f, 0.f, 0.f};
    float w2[4] = {0.f, 0.f, 0.f, 0.f};
    float a0[4] = {0.f, 0.f, 0.f, 0.f};
    float a1[4] = {0.f, 0.f, 0.f, 0.f};
    float a2[4] = {0.f, 0.f, 0.f, 0.f};

    int csl = 0;
    for (int T = 0; T < TILES; T++) {
        int bufc = T & 1;
        // (a) LDG next tile into regs (latency covered by tile body)
        float4 s0, s1, s2;
        bool have = (T + 1 < TILES);
        if (have) {
            const float4* src = projG + (T + 1) * (TK * 48);
            s0 = src[t]; s1 = src[t + 256]; s2 = src[t + 512];
        }
        // (b) consume this warp's klist range for tile T
        int js = jb[w][T], je = jb[w][T + 1];
        int np = (je - js + 1) >> 1;
        for (int p = 0; p < np; p++) {
            asm volatile("cp.async.wait_group 2;" ::: "memory");
            float4 m = ring[w][csl][h][li];
            int idx = js + 2 * p + h;
            float f = (idx < je) ? 1.f : 0.f;
            int k = klist[w][(idx < je) ? idx : (je - 1)];
            int kloc = k - T * TK;
            const float* pb = &projT[bufc][kloc][0][4 * li];
            float4 p0 = *(const float4*)(pb);
            float4 p1 = *(const float4*)(pb + 64);
            float4 p2 = *(const float4*)(pb + 128);

            float e0 = __expf(m.x) * f;
            float e1 = __expf(m.y) * f;
            float e2 = __expf(m.z) * f;
            float e3 = __expf(m.w) * f;
            dn[0] += e0; dn[1] += e1; dn[2] += e2; dn[3] += e3;
            w2[0] = fmaf(e0, e0, w2[0]); w2[1] = fmaf(e1, e1, w2[1]);
            w2[2] = fmaf(e2, e2, w2[2]); w2[3] = fmaf(e3, e3, w2[3]);
            a0[0] = fmaf(e0, p0.x, a0[0]); a0[1] = fmaf(e1, p0.y, a0[1]);
            a0[2] = fmaf(e2, p0.z, a0[2]); a0[3] = fmaf(e3, p0.w, a0[3]);
            a1[0] = fmaf(e0, p1.x, a1[0]); a1[1] = fmaf(e1, p1.y, a1[1]);
            a1[2] = fmaf(e2, p1.z, a1[2]); a1[3] = fmaf(e3, p1.w, a1[3]);
            a2[0] = fmaf(e0, p2.x, a2[0]); a2[1] = fmaf(e1, p2.y, a2[1]);
            a2[2] = fmaf(e2, p2.z, a2[2]); a2[3] = fmaf(e3, p2.w, a2[3]);

            PSTEP((csl + 3) & 3);      // overwrites a slot 3 ahead of the read
            csl = (csl + 1) & 3;
        }
        // (c) publish next tile
        if (have) {
            float4* dst = projS + (bufc ^ 1) * (TK * 48);
            dst[t] = s0; dst[t + 256] = s1; dst[t + 512] = s2;
        }
        __syncthreads();
    }
    asm volatile("cp.async.wait_group 0;" ::: "memory");
#undef PSTEP

    // ---- combine half-warp partitions, write ao (overlaps projT) ----
    #pragma unroll
    for (int i = 0; i < 4; i++) {
        dn[i] += __shfl_down_sync(0xffffffffu, dn[i], 16);
        w2[i] += __shfl_down_sync(0xffffffffu, w2[i], 16);
        a0[i] += __shfl_down_sync(0xffffffffu, a0[i], 16);
        a1[i] += __shfl_down_sync(0xffffffffu, a1[i], 16);
        a2[i] += __shfl_down_sync(0xffffffffu, a2[i], 16);
    }
    if (h == 0) {
        #pragma unroll
        for (int i = 0; i < 4; i++) {
            float s = sqrtf(w2[i]) / (dn[i] * dn[i]);
            aoS[(w * 3 + 0) * 64 + 4 * li + i] = a0[i] * s;
            aoS[(w * 3 + 1) * 64 + 4 * li + i] = a1[i] * s;
            aoS[(w * 3 + 2) * 64 + 4 * li + i] = a2[i] * s;
        }
    }
    // stage Wt (transposed W_attn) into the union region
    for (int i = t; i < 4096; i += 256) {
        WtS[(i & 63) * 65 + (i >> 6)] = Wa[i];
    }
    __syncthreads();

    // ---- epilogue: out[(q,c),d] = sum_e ao[(q,c)][e] * Wa[d][e] ----
    int d = t & 63;
    int g = t >> 6;                    // 0..3 -> 6 rows each (24 rows)
    float acc[6];
    #pragma unroll
    for (int jj = 0; jj < 6; jj++) acc[jj] = 0.f;
    #pragma unroll 4
    for (int e = 0; e < 64; e++) {
        float wt = WtS[e * 65 + d];
        #pragma unroll
        for (int jj = 0; jj < 6; jj++) {
            acc[jj] = fmaf(aoS[(g + 4 * jj) * 64 + e], wt, acc[jj]);
        }
    }
    float* orow = out + ((size_t)(b * NQ + qbase) * 3) * 64;
    #pragma unroll
    for (int jj = 0; jj < 6; jj++) {
        int r = g + 4 * jj;            // r = q_local*3 + c
        orow[r * 64 + d] = acc[jj];
    }
}

extern "C" void kernel_launch(void* const* d_in, const int* in_sizes, int n_in,
                              void* d_out, int out_size) {
    const float* v_equi   = (const float*)d_in[0];
    const float* messages = (const float*)d_in[1];
    const int*   adj_mask = (const int*)d_in[2];
    const float* W_coord  = (const float*)d_in[3];
    const float* W_attn   = (const float*)d_in[4];
    float* out = (float*)d_out;

    proj_kernel<<<768, 128>>>(v_equi, W_coord);
    attn_kernel<<<BB * (NQ / 8), 256>>>(messages, adj_mask, W_attn, out);
}

// round 8
// speedup vs baseline: 1.2072x; 1.2072x over previous
#include <cuda_runtime.h>
#include <math.h>

#define BB  16
#define NQ  256
#define NKV 256
#define DD  64
#define TILES 16
#define TK 16

__device__ float g_proj[BB * NKV * 3 * DD];

// ---------------------------------------------------------------------------
// Kernel A: proj = v_equi @ W_coord^T  (12288 rows of 64). grid=768, one
// 4-row quad per warp; v loads issued before Wt staging to overlap.
// ---------------------------------------------------------------------------
__global__ void __launch_bounds__(128) proj_kernel(const float* __restrict__ v,
                                                   const float* __restrict__ Wc) {
    __shared__ __align__(16) float Wt[64 * 66];
    __shared__ __align__(16) float vbuf[4][4][64];

    int t = threadIdx.x;
    int w = t >> 5, l = t & 31;
    int qd = blockIdx.x * 4 + w;

    float2 v0 = ((const float2*)(v + (size_t)(qd * 4 + 0) * 64))[l];
    float2 v1 = ((const float2*)(v + (size_t)(qd * 4 + 1) * 64))[l];
    float2 v2 = ((const float2*)(v + (size_t)(qd * 4 + 2) * 64))[l];
    float2 v3 = ((const float2*)(v + (size_t)(qd * 4 + 3) * 64))[l];

    for (int i = t; i < 4096; i += 128) {
        Wt[(i & 63) * 66 + (i >> 6)] = Wc[i];
    }

    vbuf[w][0][2 * l] = v0.x;  vbuf[w][0][2 * l + 1] = v0.y;
    vbuf[w][1][2 * l] = v1.x;  vbuf[w][1][2 * l + 1] = v1.y;
    vbuf[w][2][2 * l] = v2.x;  vbuf[w][2][2 * l + 1] = v2.y;
    vbuf[w][3][2 * l] = v3.x;  vbuf[w][3][2 * l + 1] = v3.y;
    __syncthreads();

    float ax[4] = {0.f, 0.f, 0.f, 0.f};
    float ay[4] = {0.f, 0.f, 0.f, 0.f};
    #pragma unroll
    for (int e4 = 0; e4 < 16; e4++) {
        float4 va[4];
        #pragma unroll
        for (int r = 0; r < 4; r++) va[r] = *(const float4*)&vbuf[w][r][e4 * 4];
        #pragma unroll
        for (int i = 0; i < 4; i++) {
            float2 wt = *(const float2*)(Wt + (e4 * 4 + i) * 66 + 2 * l);
            #pragma unroll
            for (int r = 0; r < 4; r++) {
                float fr = ((const float*)&va[r])[i];
                ax[r] = fmaf(fr, wt.x, ax[r]);
                ay[r] = fmaf(fr, wt.y, ay[r]);
            }
        }
    }
    #pragma unroll
    for (int r = 0; r < 4; r++) {
        ((float2*)(g_proj + (size_t)(qd * 4 + r) * 64))[l] = make_float2(ax[r], ay[r]);
    }
}

// ---------------------------------------------------------------------------
// Main kernel. CTA = (b, 8 q's), 8 warps, grid 512. k-space in 16 tiles of 16;
// each tile's proj (12KB) cp.async-staged to smem once per CTA and shared by
// all 8 q-warps (proj L2 traffic /8). One ACTIVE k per warp-iteration (no pair
// padding, no mask multiply, no half-warp shuffle). msg via 3-stage register
// pipeline (distance 3). One cp.async commit + one wait per TILE.
// ---------------------------------------------------------------------------
__global__ void __launch_bounds__(256, 4) attn_kernel(const float* __restrict__ msg,
                                                      const int*   __restrict__ adjm,
                                                      const float* __restrict__ Wa,
                                                      float*       __restrict__ out) {
    __shared__ __align__(16) float projT[2][TK][3][64];      // 24KB, overlaid later
    __shared__ unsigned char  klist[8][NKV + 8];             // 2.1KB
    __shared__ unsigned short jb[8][TILES + 1];

    float* WtS = &projT[0][0][0][0];          // 64*65 = 4160 floats
    float* aoS = WtS + 4160;                  // 24*64 = 1536 floats (total 5696 < 6144)

    int t = threadIdx.x;
    int w = t >> 5, l = t & 31;
    int b = blockIdx.x >> 5;
    int qbase = (blockIdx.x & 31) << 3;
    int q = qbase + w;

    const float2* msg2   = (const float2*)msg + (size_t)(b * NQ + q) * (NKV * 32);
    const float4* projG4 = (const float4*)g_proj + (size_t)b * (NKV * 48);
    float4* projS4 = (float4*)&projT[0][0][0][0];

#define CP16(dst_, src_)                                                        \
    asm volatile("cp.async.cg.shared.global [%0], [%1], 16;"                    \
                 :: "r"((unsigned)__cvta_generic_to_shared(dst_)), "l"(src_) : "memory")

    // stage proj tile 0 (768 float4 / 256 threads = 3 each)
    CP16(projS4 + t,       projG4 + t);
    CP16(projS4 + t + 256, projG4 + t + 256);
    CP16(projS4 + t + 512, projG4 + t + 512);
    asm volatile("cp.async.commit_group;" ::: "memory");

    // ---- build mask, compact klist, tile boundaries ----
    const int* arow = adjm + (b * NQ + q) * NKV;
    unsigned mask[8];
    unsigned any = 0u;
    #pragma unroll
    for (int c = 0; c < 8; c++) {
        mask[c] = __ballot_sync(0xffffffffu, arow[c * 32 + l] != 0);
        any |= mask[c];
    }
    if (!any) {
        #pragma unroll
        for (int c = 0; c < 8; c++) mask[c] = 0xffffffffu;
    }
    int cnt = 0;
    #pragma unroll
    for (int c = 0; c < 8; c++) {
        unsigned m = mask[c];
        if ((m >> l) & 1u) {
            klist[w][cnt + __popc(m & ((1u << l) - 1u))] = (unsigned char)(c * 32 + l);
        }
        cnt += __popc(m);
    }
    __syncwarp();
    if (l < 8) klist[w][cnt + l] = klist[w][cnt - 1];     // pad (cnt >= 1 always)
    if (l <= TILES) {        // jb[l] = #active k < 16*l
        int s = 0;
        #pragma unroll
        for (int c = 0; c < 8; c++) {
            if (c < (l >> 1)) s += __popc(mask[c]);
        }
        if (l & 1) s += __popc(mask[l >> 1] & 0xFFFFu);
        jb[w][l] = (unsigned short)s;
    }
    __syncwarp();

    // msg + index pipeline prologue (distance 3)
    int K0 = klist[w][0], K1 = klist[w][1], K2 = klist[w][2];
    float2 M0 = msg2[K0 * 32 + l];
    float2 M1 = msg2[K1 * 32 + l];
    float2 M2 = msg2[K2 * 32 + l];

    asm volatile("cp.async.wait_group 0;" ::: "memory");
    __syncthreads();

    float2 dn = {0.f, 0.f}, w2 = {0.f, 0.f};
    float2 A0 = {0.f, 0.f}, A1 = {0.f, 0.f}, A2 = {0.f, 0.f};

    for (int T = 0; T < TILES; T++) {
        // stage tile T+1 into the other buffer (1 commit per tile)
        if (T + 1 < TILES) {
            const float4* src = projG4 + (T + 1) * 768;
            float4* dst = projS4 + ((T + 1) & 1) * 768;
            CP16(dst + t,       src + t);
            CP16(dst + t + 256, src + t + 256);
            CP16(dst + t + 512, src + t + 512);
        }
        asm volatile("cp.async.commit_group;" ::: "memory");

        int js = jb[w][T], je = jb[w][T + 1];
        const float* pbase = &projT[T & 1][0][0][0] + 2 * l;
        int koff = T * TK;
        for (int j = js; j < je; j++) {
            float2 m = M0;  M0 = M1;  M1 = M2;
            int kc = K0;    K0 = K1;  K1 = K2;
            K2 = klist[w][j + 3];
            M2 = msg2[K2 * 32 + l];

            const float* pb = pbase + (kc - koff) * 192;
            float2 p0 = *(const float2*)(pb);
            float2 p1 = *(const float2*)(pb + 64);
            float2 p2 = *(const float2*)(pb + 128);

            float e0 = __expf(m.x);
            float e1 = __expf(m.y);
            dn.x += e0;                    dn.y += e1;
            w2.x = fmaf(e0, e0, w2.x);     w2.y = fmaf(e1, e1, w2.y);
            A0.x = fmaf(e0, p0.x, A0.x);   A0.y = fmaf(e1, p0.y, A0.y);
            A1.x = fmaf(e0, p1.x, A1.x);   A1.y = fmaf(e1, p1.y, A1.y);
            A2.x = fmaf(e0, p2.x, A2.x);   A2.y = fmaf(e1, p2.y, A2.y);
        }
        asm volatile("cp.async.wait_group 0;" ::: "memory");
        __syncthreads();
    }
#undef CP16

    // ---- finalize: attn_out = acc * sqrt(w2) / den^2  (write into overlay) ----
    float sx = sqrtf(w2.x) / (dn.x * dn.x);
    float sy = sqrtf(w2.y) / (dn.y * dn.y);
    aoS[(w * 3 + 0) * 64 + 2 * l] = A0.x * sx;  aoS[(w * 3 + 0) * 64 + 2 * l + 1] = A0.y * sy;
    aoS[(w * 3 + 1) * 64 + 2 * l] = A1.x * sx;  aoS[(w * 3 + 1) * 64 + 2 * l + 1] = A1.y * sy;
    aoS[(w * 3 + 2) * 64 + 2 * l] = A2.x * sx;  aoS[(w * 3 + 2) * 64 + 2 * l + 1] = A2.y * sy;

    // stage Wt (transposed W_attn) into the union region
    for (int i = t; i < 4096; i += 256) {
        WtS[(i & 63) * 65 + (i >> 6)] = Wa[i];
    }
    __syncthreads();

    // ---- epilogue: out[(q,c),d] = sum_e ao[(q,c)][e] * Wa[d][e] ----
    int d = t & 63;
    int g = t >> 6;                    // 0..3 -> 6 rows each (24 rows)
    float acc[6];
    #pragma unroll
    for (int jj = 0; jj < 6; jj++) acc[jj] = 0.f;
    #pragma unroll 4
    for (int e = 0; e < 64; e++) {
        float wt = WtS[e * 65 + d];
        #pragma unroll
        for (int jj = 0; jj < 6; jj++) {
            acc[jj] = fmaf(aoS[(g + 4 * jj) * 64 + e], wt, acc[jj]);
        }
    }
    float* orow = out + ((size_t)(b * NQ + qbase) * 3) * 64;
    #pragma unroll
    for (int jj = 0; jj < 6; jj++) {
        int r = g + 4 * jj;            // r = q_local*3 + c
        orow[r * 64 + d] = acc[jj];
    }
}

extern "C" void kernel_launch(void* const* d_in, const int* in_sizes, int n_in,
                              void* d_out, int out_size) {
    const float* v_equi   = (const float*)d_in[0];
    const float* messages = (const float*)d_in[1];
    const int*   adj_mask = (const int*)d_in[2];
    const float* W_coord  = (const float*)d_in[3];
    const float* W_attn   = (const float*)d_in[4];
    float* out = (float*)d_out;

    proj_kernel<<<768, 128>>>(v_equi, W_coord);
    attn_kernel<<<BB * (NQ / 8), 256>>>(messages, adj_mask, W_attn, out);
}